// round 13
// baseline (speedup 1.0000x reference)
#include <cuda_runtime.h>
#include <cuda_bf16.h>
#include <cstdint>

#define NB   2
#define NTOK 8000
#define DM   256
#define NH   8
#define DH   32
#define KMAX 3200

#define WK_OFF 262144
#define WV_OFF 524288
#define WO_OFF 786432
#define W1_OFF 1048576
#define W2_OFF 2097152
#define WB_TOTAL 3145728

// ---------------- scratch (device globals; no allocations) ----------------
__device__ float g_x[NB * KMAX * DM];          // rank-ordered residual stream (stride KMAX/batch)
__device__ float g_h[NB * KMAX * DM];          // bf16 h (rank-ordered)
__device__ float g_q[NB * KMAX * DM];          // bf16 q (dense)
__device__ float g_k[NB * KMAX * DM];          // bf16 k (dense)
__device__ float g_v[NB * KMAX * DM];          // bf16 v (dense)
__device__ float g_a[NB * KMAX * DM];          // bf16 attn out (dense)
__device__ float g_f[NB * KMAX * 4 * DM];      // bf16 ffn intermediate (dense)
__device__ __nv_bfloat16 g_wb[WB_TOTAL];       // converted weights
__device__ int   g_idx[NB * NTOK];

// ---------------- fast math helpers ----------------
__device__ __forceinline__ float mufu_ex2(float z) {
    float r;
    asm("ex2.approx.ftz.f32 %0, %1;" : "=f"(r) : "f"(z));
    return r;
}

__device__ __forceinline__ float mufu_rcp(float z) {
    float r;
    asm("rcp.approx.ftz.f32 %0, %1;" : "=f"(r) : "f"(z));
    return r;
}

__device__ __forceinline__ float gelu_f(float x) {
    float u = 1.5957691216057308f * fmaf(0.044715f * x * x, x, x);
    return x * mufu_rcp(1.0f + mufu_ex2(u * -1.4426950408889634f));
}

__device__ __forceinline__ uint32_t pack_bf16(float lo, float hi) {
    uint32_t d;
    asm("cvt.rn.bf16x2.f32 %0, %1, %2;" : "=r"(d) : "f"(hi), "f"(lo));
    return d;
}

__device__ __forceinline__ void mma_bf16(float* d, const uint32_t* a, uint32_t b0, uint32_t b1) {
    asm volatile(
        "mma.sync.aligned.m16n8k16.row.col.f32.bf16.bf16.f32 "
        "{%0,%1,%2,%3}, {%4,%5,%6,%7}, {%8,%9}, {%0,%1,%2,%3};"
        : "+f"(d[0]), "+f"(d[1]), "+f"(d[2]), "+f"(d[3])
        : "r"(a[0]), "r"(a[1]), "r"(a[2]), "r"(a[3]), "r"(b0), "r"(b1));
}

__device__ __forceinline__ void ldsm_x4(uint32_t* r, uint32_t addr) {
    asm volatile("ldmatrix.sync.aligned.m8n8.x4.shared.b16 {%0,%1,%2,%3}, [%4];"
                 : "=r"(r[0]), "=r"(r[1]), "=r"(r[2]), "=r"(r[3]) : "r"(addr));
}

__device__ __forceinline__ void ldsm_x4t(uint32_t* r, uint32_t addr) {
    asm volatile("ldmatrix.sync.aligned.m8n8.x4.trans.shared.b16 {%0,%1,%2,%3}, [%4];"
                 : "=r"(r[0]), "=r"(r[1]), "=r"(r[2]), "=r"(r[3]) : "r"(addr));
}

__device__ __forceinline__ void cp16(uint32_t dst, const void* src, bool pred) {
    int sz = pred ? 16 : 0;
    asm volatile("cp.async.cg.shared.global [%0], [%1], 16, %2;"
                 :: "r"(dst), "l"(src), "r"(sz));
}
#define CP_COMMIT() asm volatile("cp.async.commit_group;")
#define CP_WAIT0()  asm volatile("cp.async.wait_group 0;")
#define CP_WAIT1()  asm volatile("cp.async.wait_group 1;")

// rank-space row mapping: dense active row r (0..2kc) -> storage row in [b*KMAX + rank]
__device__ __forceinline__ int row_map(int r, int kc) {
    return r + ((r >= kc) ? (KMAX - kc) : 0);
}

// ---------------- utility kernels ----------------
__global__ void copy_kernel(const float4* __restrict__ in, float4* __restrict__ out, int n4) {
    int i = blockIdx.x * blockDim.x + threadIdx.x;
    if (i < n4) out[i] = in[i];
}

__global__ void cvtw_kernel(const float4* __restrict__ wq, const float4* __restrict__ wk,
                            const float4* __restrict__ wv, const float4* __restrict__ wo,
                            const float4* __restrict__ w1, const float4* __restrict__ w2,
                            uint2* __restrict__ dst) {
    int i = blockIdx.x * 256 + threadIdx.x;
    const float4* src;
    int off;
    if (i < 65536)        { src = wq; off = i; }
    else if (i < 131072)  { src = wk; off = i - 65536; }
    else if (i < 196608)  { src = wv; off = i - 131072; }
    else if (i < 262144)  { src = wo; off = i - 196608; }
    else if (i < 524288)  { src = w1; off = i - 262144; }
    else                  { src = w2; off = i - 524288; }
    float4 v = src[off];
    dst[i] = make_uint2(pack_bf16(v.x, v.y), pack_bf16(v.z, v.w));
}

__global__ void rank_kernel(const float* __restrict__ sal, int* __restrict__ idx) {
    __shared__ float tile[256];
    int b = blockIdx.y;
    int i = blockIdx.x * 256 + threadIdx.x;
    float v = (i < NTOK) ? sal[b * NTOK + i] : 0.0f;
    int rank = 0;
    const int NT = (NTOK + 255) / 256;
    for (int t = 0; t < NT; t++) {
        int j = t * 256 + threadIdx.x;
        tile[threadIdx.x] = (j < NTOK) ? sal[b * NTOK + j] : -3.402823466e38f;
        __syncthreads();
        int base = t * 256;
#pragma unroll 8
        for (int jj = 0; jj < 256; jj++) {
            float w = tile[jj];
            rank += (w > v) || (w == v && (base + jj) < i);
        }
        __syncthreads();
    }
    if (i < NTOK) idx[b * NTOK + rank] = i;
}

// final scatter: rank-ordered px -> feature bank (all KMAX ranks, both batches)
__global__ void fscatter_kernel(const float* __restrict__ px, const int* __restrict__ idx,
                                float* __restrict__ out) {
    int row = blockIdx.x * 8 + (threadIdx.x >> 5);
    if (row >= NB * KMAX) return;
    int lane = threadIdx.x & 31;
    int b = (row >= KMAX) ? 1 : 0;
    int rank = row - b * KMAX;
    int dst = idx[b * NTOK + rank];
    const float* sp = px + (size_t)row * DM + lane * 8;
    float* dp = out + ((size_t)b * NTOK + dst) * DM + lane * 8;
    float4 v0 = *(const float4*)sp;
    float4 v1 = *(const float4*)(sp + 4);
    *(float4*)dp = v0;
    *(float4*)(dp + 4) = v1;
}

// ---------------- warp-per-token LayerNorm (bf16 h output, rank space) ----------------
// GATHER=1: read bank via idx, write px[rm] and h[rm].  GATHER=0: read px[rm], write h[rm].
template <int GATHER>
__global__ void lnw_kernel(const float* __restrict__ src, const int* __restrict__ idx,
                           const float* __restrict__ gam, const float* __restrict__ bet,
                           float* __restrict__ px, __nv_bfloat16* __restrict__ h, int kc, int M) {
    int row = blockIdx.x * 8 + (threadIdx.x >> 5);
    if (row >= M) return;
    int lane = threadIdx.x & 31;
    int rm = row_map(row, kc);
    const float* p;
    if (GATHER) {
        int b = (row >= kc) ? 1 : 0;
        int i = row - b * kc;
        int sr = idx[b * NTOK + i];
        p = src + ((size_t)b * NTOK + sr) * DM + lane * 8;
    } else {
        p = src + (size_t)rm * DM + lane * 8;
    }
    float4 v0 = *(const float4*)p;
    float4 v1 = *(const float4*)(p + 4);
    if (GATHER) {
        float* xp = px + (size_t)rm * DM + lane * 8;
        *(float4*)xp = v0;
        *(float4*)(xp + 4) = v1;
    }
    float s = v0.x + v0.y + v0.z + v0.w + v1.x + v1.y + v1.z + v1.w;
#pragma unroll
    for (int o = 16; o; o >>= 1) s += __shfl_xor_sync(0xffffffffu, s, o);
    float mu = s * (1.0f / DM);
    float c[8] = {v0.x - mu, v0.y - mu, v0.z - mu, v0.w - mu,
                  v1.x - mu, v1.y - mu, v1.z - mu, v1.w - mu};
    float vs = 0.f;
#pragma unroll
    for (int j = 0; j < 8; j++) vs = fmaf(c[j], c[j], vs);
#pragma unroll
    for (int o = 16; o; o >>= 1) vs += __shfl_xor_sync(0xffffffffu, vs, o);
    float inv = rsqrtf(vs * (1.0f / DM) + 1e-5f);
    float4 gg0 = *(const float4*)(gam + lane * 8);
    float4 gg1 = *(const float4*)(gam + lane * 8 + 4);
    float4 bb0 = *(const float4*)(bet + lane * 8);
    float4 bb1 = *(const float4*)(bet + lane * 8 + 4);
    float r0 = fmaf(c[0] * inv, gg0.x, bb0.x), r1 = fmaf(c[1] * inv, gg0.y, bb0.y);
    float r2 = fmaf(c[2] * inv, gg0.z, bb0.z), r3 = fmaf(c[3] * inv, gg0.w, bb0.w);
    float r4 = fmaf(c[4] * inv, gg1.x, bb1.x), r5 = fmaf(c[5] * inv, gg1.y, bb1.y);
    float r6 = fmaf(c[6] * inv, gg1.z, bb1.z), r7 = fmaf(c[7] * inv, gg1.w, bb1.w);
    uint4 o4;
    o4.x = pack_bf16(r0, r1); o4.y = pack_bf16(r2, r3);
    o4.z = pack_bf16(r4, r5); o4.w = pack_bf16(r6, r7);
    *(uint4*)(h + (size_t)rm * DM + lane * 8) = o4;
}

// ---------------- bf16 ldmatrix GEMM, 3-stage cp.async pipeline ----------------
struct BGemmCtx {
    uint32_t a_base, b_base;
    int arow, akq, brow, bnc;
    int a_row_off, a_kh;
    int wm, wn;
};

#define A_STAGE_B (128 * 40 * 2)
#define B_STAGE_B (32 * 72 * 2)

__device__ __forceinline__ BGemmCtx make_ctx(void* As, void* Bs) {
    int tid = threadIdx.x;
    int warp = tid >> 5, lane = tid & 31;
    BGemmCtx c;
    c.a_base = (uint32_t)__cvta_generic_to_shared(As);
    c.b_base = (uint32_t)__cvta_generic_to_shared(Bs);
    c.arow = tid >> 1;
    c.akq = (tid & 1) * 16;
    c.brow = tid >> 3;
    c.bnc = (tid & 7) * 8;
    c.a_row_off = (lane & 7) + ((lane >> 3) & 1) * 8;
    c.a_kh = (lane >> 4) * 8;
    c.wm = (warp & 3) * 32;
    c.wn = (warp >> 2) * 32;
    return c;
}

template <int MAPA>
__device__ __forceinline__ void bgemm_stage_load(
    const __nv_bfloat16* __restrict__ A, const __nv_bfloat16* __restrict__ W,
    int M, int N, int K, int m0, int n0, const BGemmCtx& c, int s, int nit, int kc) {
    if (s < nit) {
        int sb = s % 3;
        int k0 = s << 5;
        int gr = m0 + c.arow;
        bool pr = gr < M;
        int grm = MAPA ? row_map(gr, kc) : gr;
        cp16(c.a_base + sb * A_STAGE_B + (c.arow * 40 + c.akq) * 2,
             A + (size_t)grm * K + k0 + c.akq, pr);
        cp16(c.a_base + sb * A_STAGE_B + (c.arow * 40 + c.akq + 8) * 2,
             A + (size_t)grm * K + k0 + c.akq + 8, pr);
        cp16(c.b_base + sb * B_STAGE_B + (c.brow * 72 + c.bnc) * 2,
             W + (size_t)(k0 + c.brow) * N + n0 + c.bnc, true);
    }
    CP_COMMIT();
}

template <int MAPA>
__device__ __forceinline__ void bgemm_mainloop(
    const __nv_bfloat16* __restrict__ A, const __nv_bfloat16* __restrict__ W,
    int M, int N, int K, int m0, int n0, const BGemmCtx& c, float acc[2][4][4], int kc) {
    int nit = K >> 5;
    bgemm_stage_load<MAPA>(A, W, M, N, K, m0, n0, c, 0, nit, kc);
    bgemm_stage_load<MAPA>(A, W, M, N, K, m0, n0, c, 1, nit, kc);
    for (int it = 0; it < nit; it++) {
        CP_WAIT1();
        __syncthreads();
        bgemm_stage_load<MAPA>(A, W, M, N, K, m0, n0, c, it + 2, nit, kc);
        int sb = it % 3;
        uint32_t ab = c.a_base + sb * A_STAGE_B;
        uint32_t bb = c.b_base + sb * B_STAGE_B;
#pragma unroll
        for (int ks = 0; ks < 2; ks++) {
            uint32_t af[2][4], bf[2][4];
#pragma unroll
            for (int mt = 0; mt < 2; mt++)
                ldsm_x4(af[mt], ab + ((c.wm + mt * 16 + c.a_row_off) * 40 + ks * 16 + c.a_kh) * 2);
#pragma unroll
            for (int nb = 0; nb < 2; nb++)
                ldsm_x4t(bf[nb], bb + ((ks * 16 + c.a_row_off) * 72 + c.wn + nb * 16 + c.a_kh) * 2);
#pragma unroll
            for (int mt = 0; mt < 2; mt++)
#pragma unroll
                for (int n8 = 0; n8 < 4; n8++)
                    mma_bf16(acc[mt][n8], af[mt], bf[n8 >> 1][(n8 & 1) * 2], bf[n8 >> 1][(n8 & 1) * 2 + 1]);
        }
    }
}

// EPI: 1 = f32 residual add into Outv (row-mapped if MAPC), 2 = gelu -> bf16 Outv (dense)
template <int EPI, int MAPA, int MAPC>
__global__ void __launch_bounds__(256)
bgemm_kernel(const __nv_bfloat16* __restrict__ A, const __nv_bfloat16* __restrict__ W,
             void* __restrict__ Outv, int M, int N, int K, int kc) {
    __shared__ __nv_bfloat16 As[3][128][40];
    __shared__ __nv_bfloat16 Bs[3][32][72];
    int m0 = blockIdx.x * 128, n0 = blockIdx.y * 64;
    BGemmCtx c = make_ctx(As, Bs);
    float acc[2][4][4] = {};
    bgemm_mainloop<MAPA>(A, W, M, N, K, m0, n0, c, acc, kc);

    int lane = threadIdx.x & 31, g = lane >> 2, tg = lane & 3;
#pragma unroll
    for (int mt = 0; mt < 2; mt++) {
#pragma unroll
        for (int half = 0; half < 2; half++) {
            int r = m0 + c.wm + mt * 16 + g + half * 8;
            if (r >= M) continue;
            int rc = MAPC ? row_map(r, kc) : r;
#pragma unroll
            for (int n8 = 0; n8 < 4; n8++) {
                int col = n0 + c.wn + n8 * 8 + 2 * tg;
                float c0 = acc[mt][n8][half * 2 + 0];
                float c1 = acc[mt][n8][half * 2 + 1];
                if (EPI == 1) {
                    float* cp = (float*)Outv + (size_t)rc * N + col;
                    float2 o = *(float2*)cp;
                    o.x += c0; o.y += c1;
                    *(float2*)cp = o;
                } else {  // EPI == 2
                    *(uint32_t*)((__nv_bfloat16*)Outv + (size_t)rc * N + col) =
                        pack_bf16(gelu_f(c0), gelu_f(c1));
                }
            }
        }
    }
}

__global__ void __launch_bounds__(256)
qkvb_kernel(const __nv_bfloat16* __restrict__ A,
            const __nv_bfloat16* __restrict__ Wq, const __nv_bfloat16* __restrict__ Wk,
            const __nv_bfloat16* __restrict__ Wv,
            __nv_bfloat16* __restrict__ Oq, __nv_bfloat16* __restrict__ Ok,
            __nv_bfloat16* __restrict__ Ov, int M, int kc, float qscale) {
    __shared__ __nv_bfloat16 As[3][128][40];
    __shared__ __nv_bfloat16 Bs[3][32][72];
    int which = blockIdx.y >> 2;
    int n0 = (blockIdx.y & 3) * 64;
    int m0 = blockIdx.x * 128;
    const __nv_bfloat16* W = (which == 0) ? Wq : ((which == 1) ? Wk : Wv);
    __nv_bfloat16* Ob = (which == 0) ? Oq : ((which == 1) ? Ok : Ov);
    float sc = (which == 0) ? qscale : 1.0f;
    BGemmCtx c = make_ctx(As, Bs);
    float acc[2][4][4] = {};
    bgemm_mainloop<1>(A, W, M, DM, DM, m0, n0, c, acc, kc);  // A = h (rank-mapped)

    int lane = threadIdx.x & 31, g = lane >> 2, tg = lane & 3;
#pragma unroll
    for (int mt = 0; mt < 2; mt++) {
#pragma unroll
        for (int half = 0; half < 2; half++) {
            int r = m0 + c.wm + mt * 16 + g + half * 8;
            if (r >= M) continue;
#pragma unroll
            for (int n8 = 0; n8 < 4; n8++) {
                int col = n0 + c.wn + n8 * 8 + 2 * tg;
                *(uint32_t*)(Ob + (size_t)r * DM + col) =
                    pack_bf16(acc[mt][n8][half * 2 + 0] * sc, acc[mt][n8][half * 2 + 1] * sc);
            }
        }
    }
}

// ---------------- flash attention: q-tile 128, 128-key 3-stage cp.async ----------------
// grid (ceil(kc/128), NH, NB), 256 threads = 8 warps. Dynamic smem: 6 * 128*40 bf16.
__global__ void __launch_bounds__(256) attn_mma_kernel(const __nv_bfloat16* __restrict__ Q,
                                                       const __nv_bfloat16* __restrict__ Kx,
                                                       const __nv_bfloat16* __restrict__ Vx,
                                                       __nv_bfloat16* __restrict__ O, int kc) {
    extern __shared__ __nv_bfloat16 dyn[];
    __nv_bfloat16* Ksm = dyn;                    // 3 stages x 128x40
    __nv_bfloat16* Vsm = dyn + 3 * 128 * 40;
    const int ST_B = 128 * 40 * 2;               // 10240 bytes per stage
    int b = blockIdx.z, hh = blockIdx.y;
    int q0 = blockIdx.x * 128;
    int tid = threadIdx.x;
    int warp = tid >> 5, lane = tid & 31, g = lane >> 2, tg = lane & 3;
    const __nv_bfloat16* Qp = Q + ((size_t)b * kc) * DM + hh * DH;
    const __nv_bfloat16* Kp = Kx + ((size_t)b * kc) * DM + hh * DH;
    const __nv_bfloat16* Vg = Vx + ((size_t)b * kc) * DM + hh * DH;

    uint32_t ksb = (uint32_t)__cvta_generic_to_shared(Ksm);
    uint32_t vsb = (uint32_t)__cvta_generic_to_shared(Vsm);
    int lrow = tid >> 2;             // 0..63
    int lch  = (tid & 3) * 8;
    int aro  = lane & 15;
    int akh  = (lane >> 4) * 8;

    // stage Q tile (128 rows) into Ksm stage 0
    {
        int gq0 = q0 + lrow, gq1 = q0 + 64 + lrow;
        cp16(ksb + (lrow * 40 + lch) * 2, Qp + (size_t)gq0 * DM + lch, gq0 < kc);
        cp16(ksb + ((lrow + 64) * 40 + lch) * 2, Qp + (size_t)gq1 * DM + lch, gq1 < kc);
    }
    CP_COMMIT();
    CP_WAIT0();
    __syncthreads();
    uint32_t qf[2][4];
    {
        int wq = warp * 16;
        ldsm_x4(qf[0], ksb + ((wq + aro) * 40 + akh) * 2);
        ldsm_x4(qf[1], ksb + ((wq + aro) * 40 + 16 + akh) * 2);
    }
    __syncthreads();  // frag reads done before stage-0 load overwrites

    float oacc[4][4] = {};
    float lsum[2] = {0.f, 0.f};
    int ntile = (kc + 127) >> 7;

    // prologue: stages 0 and 1 (one commit group per stage)
#pragma unroll
    for (int s = 0; s < 2; s++) {
        if (s < ntile) {
            int gk0 = s * 128 + lrow, gk1 = gk0 + 64;
            cp16(ksb + s * ST_B + (lrow * 40 + lch) * 2, Kp + (size_t)gk0 * DM + lch, gk0 < kc);
            cp16(ksb + s * ST_B + ((lrow + 64) * 40 + lch) * 2, Kp + (size_t)gk1 * DM + lch, gk1 < kc);
            cp16(vsb + s * ST_B + (lrow * 40 + lch) * 2, Vg + (size_t)gk0 * DM + lch, gk0 < kc);
            cp16(vsb + s * ST_B + ((lrow + 64) * 40 + lch) * 2, Vg + (size_t)gk1 * DM + lch, gk1 < kc);
        }
        CP_COMMIT();
    }

    for (int kt = 0; kt < ntile; kt++) {
        CP_WAIT1();
        __syncthreads();
        {   // prefetch stage kt+2 (empty commit past the end keeps accounting uniform)
            int s = kt + 2;
            if (s < ntile) {
                int sb = s % 3;
                int gk0 = s * 128 + lrow, gk1 = gk0 + 64;
                cp16(ksb + sb * ST_B + (lrow * 40 + lch) * 2, Kp + (size_t)gk0 * DM + lch, gk0 < kc);
                cp16(ksb + sb * ST_B + ((lrow + 64) * 40 + lch) * 2, Kp + (size_t)gk1 * DM + lch, gk1 < kc);
                cp16(vsb + sb * ST_B + (lrow * 40 + lch) * 2, Vg + (size_t)gk0 * DM + lch, gk0 < kc);
                cp16(vsb + sb * ST_B + ((lrow + 64) * 40 + lch) * 2, Vg + (size_t)gk1 * DM + lch, gk1 < kc);
            }
            CP_COMMIT();
        }
        int sb = kt % 3;

#pragma unroll
        for (int h2 = 0; h2 < 2; h2++) {
            int j0 = (kt << 7) + h2 * 64;
            if (j0 >= kc) continue;           // fully-masked half: contributes nothing
            uint32_t kb_ = ksb + sb * ST_B + h2 * (64 * 40 * 2);
            uint32_t vb_ = vsb + sb * ST_B + h2 * (64 * 40 * 2);

            // S = Q K^T : 16 q-rows x 64 keys per warp
            float sacc[8][4] = {};
#pragma unroll
            for (int ks = 0; ks < 2; ks++) {
#pragma unroll
                for (int i = 0; i < 4; i++) {
                    uint32_t br[4];
                    ldsm_x4(br, kb_ + ((i * 16 + aro) * 40 + ks * 16 + akh) * 2);
                    mma_bf16(sacc[2 * i],     qf[ks], br[0], br[2]);
                    mma_bf16(sacc[2 * i + 1], qf[ks], br[1], br[3]);
                }
            }
            if (j0 + 64 > kc) {
#pragma unroll
                for (int jn = 0; jn < 8; jn++)
                    if (j0 + 8 * jn >= kc) {
                        sacc[jn][0] = -1e30f; sacc[jn][1] = -1e30f;
                        sacc[jn][2] = -1e30f; sacc[jn][3] = -1e30f;
                    }
            }
#pragma unroll
            for (int jn = 0; jn < 8; jn++) {
                float p0 = mufu_ex2(sacc[jn][0]);
                float p1 = mufu_ex2(sacc[jn][1]);
                float p2 = mufu_ex2(sacc[jn][2]);
                float p3 = mufu_ex2(sacc[jn][3]);
                sacc[jn][0] = p0; sacc[jn][1] = p1; sacc[jn][2] = p2; sacc[jn][3] = p3;
                lsum[0] += p0 + p1;
                lsum[1] += p2 + p3;
            }
            // O += P V
#pragma unroll
            for (int s = 0; s < 4; s++) {
                uint32_t pf[4];
                pf[0] = pack_bf16(sacc[2 * s][0], sacc[2 * s][1]);
                pf[1] = pack_bf16(sacc[2 * s][2], sacc[2 * s][3]);
                pf[2] = pack_bf16(sacc[2 * s + 1][0], sacc[2 * s + 1][1]);
                pf[3] = pack_bf16(sacc[2 * s + 1][2], sacc[2 * s + 1][3]);
#pragma unroll
                for (int dv = 0; dv < 2; dv++) {
                    uint32_t br[4];
                    ldsm_x4t(br, vb_ + ((s * 16 + aro) * 40 + dv * 16 + akh) * 2);
                    mma_bf16(oacc[2 * dv],     pf, br[0], br[1]);
                    mma_bf16(oacc[2 * dv + 1], pf, br[2], br[3]);
                }
            }
        }
    }

    lsum[0] += __shfl_xor_sync(0xffffffffu, lsum[0], 1);
    lsum[0] += __shfl_xor_sync(0xffffffffu, lsum[0], 2);
    lsum[1] += __shfl_xor_sync(0xffffffffu, lsum[1], 1);
    lsum[1] += __shfl_xor_sync(0xffffffffu, lsum[1], 2);
    float inv0 = __fdividef(1.0f, lsum[0]);
    float inv1 = __fdividef(1.0f, lsum[1]);

    int qr0 = q0 + warp * 16 + g;
    int qr1 = qr0 + 8;
    if (qr0 < kc) {
        __nv_bfloat16* op = O + ((size_t)b * kc + qr0) * DM + hh * DH;
#pragma unroll
        for (int dn = 0; dn < 4; dn++)
            *(uint32_t*)(op + 8 * dn + 2 * tg) = pack_bf16(oacc[dn][0] * inv0, oacc[dn][1] * inv0);
    }
    if (qr1 < kc) {
        __nv_bfloat16* op = O + ((size_t)b * kc + qr1) * DM + hh * DH;
#pragma unroll
        for (int dn = 0; dn < 4; dn++)
            *(uint32_t*)(op + 8 * dn + 2 * tg) = pack_bf16(oacc[dn][2] * inv1, oacc[dn][3] * inv1);
    }
}

// ---------------- launch ----------------
extern "C" void kernel_launch(void* const* d_in, const int* in_sizes, int n_in,
                              void* d_out, int out_size) {
    const float* feat = (const float*)d_in[0];
    const float* sal  = (const float*)d_in[1];
    const float* Wq   = (const float*)d_in[2];
    const float* Wk   = (const float*)d_in[3];
    const float* Wv   = (const float*)d_in[4];
    const float* Wo   = (const float*)d_in[5];
    const float* W1   = (const float*)d_in[6];
    const float* W2   = (const float*)d_in[7];
    const float* g1   = (const float*)d_in[8];
    const float* b1   = (const float*)d_in[9];
    const float* g2   = (const float*)d_in[10];
    const float* b2   = (const float*)d_in[11];
    float* out = (float*)d_out;

    float *px, *ph, *pq, *pk, *pv, *pa, *pf;
    __nv_bfloat16* pwb;
    int* pidx;
    cudaGetSymbolAddress((void**)&px, g_x);
    cudaGetSymbolAddress((void**)&ph, g_h);
    cudaGetSymbolAddress((void**)&pq, g_q);
    cudaGetSymbolAddress((void**)&pk, g_k);
    cudaGetSymbolAddress((void**)&pv, g_v);
    cudaGetSymbolAddress((void**)&pa, g_a);
    cudaGetSymbolAddress((void**)&pf, g_f);
    cudaGetSymbolAddress((void**)&pwb, g_wb);
    cudaGetSymbolAddress((void**)&pidx, g_idx);

    __nv_bfloat16* hb = (__nv_bfloat16*)ph;
    __nv_bfloat16* qb = (__nv_bfloat16*)pq;
    __nv_bfloat16* kb = (__nv_bfloat16*)pk;
    __nv_bfloat16* vb = (__nv_bfloat16*)pv;
    __nv_bfloat16* ab = (__nv_bfloat16*)pa;
    __nv_bfloat16* fb = (__nv_bfloat16*)pf;

    const int ATTN_SMEM = 6 * 128 * 40 * 2;  // 61440 bytes
    cudaFuncSetAttribute(attn_mma_kernel, cudaFuncAttributeMaxDynamicSharedMemorySize, ATTN_SMEM);

    // 1/sqrt(32) * log2(e): softmax done in exp2 domain
    const float qscale = 0.17677669529663687f * 1.4426950408889634f;
    const int n4 = NB * NTOK * DM / 4;
    copy_kernel<<<(n4 + 255) / 256, 256>>>((const float4*)feat, (float4*)out, n4);
    rank_kernel<<<dim3((NTOK + 255) / 256, NB), 256>>>(sal, pidx);
    cvtw_kernel<<<WB_TOTAL / 4 / 256, 256>>>((const float4*)Wq, (const float4*)Wk,
                                             (const float4*)Wv, (const float4*)Wo,
                                             (const float4*)W1, (const float4*)W2, (uint2*)pwb);

    static const int KCNT[4] = {3200, 2400, 2000, 1600};
    for (int l = 0; l < 4; l++) {
        int kc = KCNT[l];
        int M = NB * kc;
        int gx128 = (M + 127) / 128;
        const __nv_bfloat16* wq_l = pwb + (size_t)l * 65536;
        const __nv_bfloat16* wk_l = pwb + WK_OFF + (size_t)l * 65536;
        const __nv_bfloat16* wv_l = pwb + WV_OFF + (size_t)l * 65536;
        const __nv_bfloat16* wo_l = pwb + WO_OFF + (size_t)l * 65536;
        const __nv_bfloat16* w1_l = pwb + W1_OFF + (size_t)l * 262144;
        const __nv_bfloat16* w2_l = pwb + W2_OFF + (size_t)l * 262144;

        if (l == 0)
            lnw_kernel<1><<<(M + 7) / 8, 256>>>(out, pidx, g1, b1, px, hb, kc, M);
        else
            lnw_kernel<0><<<(M + 7) / 8, 256>>>(px, nullptr, g1 + l * DM, b1 + l * DM, nullptr, hb, kc, M);
        qkvb_kernel<<<dim3(gx128, 12), 256>>>(hb, wq_l, wk_l, wv_l, qb, kb, vb, M, kc, qscale);
        attn_mma_kernel<<<dim3((kc + 127) / 128, NH, NB), 256, ATTN_SMEM>>>(qb, kb, vb, ab, kc);
        bgemm_kernel<1, 0, 1><<<dim3(gx128, 4), 256>>>(ab, wo_l, px, M, DM, DM, kc);
        lnw_kernel<0><<<(M + 7) / 8, 256>>>(px, nullptr, g2 + l * DM, b2 + l * DM, nullptr, hb, kc, M);
        bgemm_kernel<2, 1, 0><<<dim3(gx128, 16), 256>>>(hb, w1_l, fb, M, 4 * DM, DM, kc);
        bgemm_kernel<1, 0, 1><<<dim3(gx128, 4), 256>>>(fb, w2_l, px, M, DM, 4 * DM, kc);
    }
    fscatter_kernel<<<(NB * KMAX + 7) / 8, 256>>>(px, pidx, out);
}

// round 14
// speedup vs baseline: 1.0132x; 1.0132x over previous
#include <cuda_runtime.h>
#include <cuda_bf16.h>
#include <cstdint>

#define NB   2
#define NTOK 8000
#define DM   256
#define NH   8
#define DH   32
#define KMAX 3200

#define WK_OFF 262144
#define WV_OFF 524288
#define WO_OFF 786432
#define W1_OFF 1048576
#define W2_OFF 2097152
#define WB_TOTAL 3145728

// ---------------- scratch (device globals; no allocations) ----------------
__device__ float g_x[NB * KMAX * DM];          // rank-ordered residual stream (stride KMAX/batch)
__device__ float g_h[NB * KMAX * DM];          // bf16 h (rank-ordered)
__device__ float g_q[NB * KMAX * DM];          // bf16 q (dense)
__device__ float g_k[NB * KMAX * DM];          // bf16 k (dense)
__device__ float g_v[NB * KMAX * DM];          // bf16 v (dense)
__device__ float g_a[NB * KMAX * DM];          // bf16 attn out (dense)
__device__ float g_f[NB * KMAX * 4 * DM];      // bf16 ffn intermediate (dense)
__device__ __nv_bfloat16 g_wb[WB_TOTAL];       // converted weights
__device__ int   g_idx[NB * NTOK];

// ---------------- fast math helpers ----------------
__device__ __forceinline__ float mufu_ex2(float z) {
    float r;
    asm("ex2.approx.ftz.f32 %0, %1;" : "=f"(r) : "f"(z));
    return r;
}

__device__ __forceinline__ float mufu_rcp(float z) {
    float r;
    asm("rcp.approx.ftz.f32 %0, %1;" : "=f"(r) : "f"(z));
    return r;
}

__device__ __forceinline__ float gelu_f(float x) {
    float u = 1.5957691216057308f * fmaf(0.044715f * x * x, x, x);
    return x * mufu_rcp(1.0f + mufu_ex2(u * -1.4426950408889634f));
}

__device__ __forceinline__ uint32_t pack_bf16(float lo, float hi) {
    uint32_t d;
    asm("cvt.rn.bf16x2.f32 %0, %1, %2;" : "=r"(d) : "f"(hi), "f"(lo));
    return d;
}

__device__ __forceinline__ void mma_bf16(float* d, const uint32_t* a, uint32_t b0, uint32_t b1) {
    asm volatile(
        "mma.sync.aligned.m16n8k16.row.col.f32.bf16.bf16.f32 "
        "{%0,%1,%2,%3}, {%4,%5,%6,%7}, {%8,%9}, {%0,%1,%2,%3};"
        : "+f"(d[0]), "+f"(d[1]), "+f"(d[2]), "+f"(d[3])
        : "r"(a[0]), "r"(a[1]), "r"(a[2]), "r"(a[3]), "r"(b0), "r"(b1));
}

__device__ __forceinline__ void ldsm_x4(uint32_t* r, uint32_t addr) {
    asm volatile("ldmatrix.sync.aligned.m8n8.x4.shared.b16 {%0,%1,%2,%3}, [%4];"
                 : "=r"(r[0]), "=r"(r[1]), "=r"(r[2]), "=r"(r[3]) : "r"(addr));
}

__device__ __forceinline__ void ldsm_x4t(uint32_t* r, uint32_t addr) {
    asm volatile("ldmatrix.sync.aligned.m8n8.x4.trans.shared.b16 {%0,%1,%2,%3}, [%4];"
                 : "=r"(r[0]), "=r"(r[1]), "=r"(r[2]), "=r"(r[3]) : "r"(addr));
}

__device__ __forceinline__ void cp16(uint32_t dst, const void* src, bool pred) {
    int sz = pred ? 16 : 0;
    asm volatile("cp.async.cg.shared.global [%0], [%1], 16, %2;"
                 :: "r"(dst), "l"(src), "r"(sz));
}
#define CP_COMMIT() asm volatile("cp.async.commit_group;")
#define CP_WAIT0()  asm volatile("cp.async.wait_group 0;")
#define CP_WAIT1()  asm volatile("cp.async.wait_group 1;")

// rank-space row mapping: dense active row r (0..2kc) -> storage row in [b*KMAX + rank]
__device__ __forceinline__ int row_map(int r, int kc) {
    return r + ((r >= kc) ? (KMAX - kc) : 0);
}

// ---------------- utility kernels ----------------
__global__ void copy_kernel(const float4* __restrict__ in, float4* __restrict__ out, int n4) {
    int i = blockIdx.x * blockDim.x + threadIdx.x;
    if (i < n4) out[i] = in[i];
}

__global__ void cvtw_kernel(const float4* __restrict__ wq, const float4* __restrict__ wk,
                            const float4* __restrict__ wv, const float4* __restrict__ wo,
                            const float4* __restrict__ w1, const float4* __restrict__ w2,
                            uint2* __restrict__ dst) {
    int i = blockIdx.x * 256 + threadIdx.x;
    const float4* src;
    int off;
    if (i < 65536)        { src = wq; off = i; }
    else if (i < 131072)  { src = wk; off = i - 65536; }
    else if (i < 196608)  { src = wv; off = i - 131072; }
    else if (i < 262144)  { src = wo; off = i - 196608; }
    else if (i < 524288)  { src = w1; off = i - 262144; }
    else                  { src = w2; off = i - 524288; }
    float4 v = src[off];
    dst[i] = make_uint2(pack_bf16(v.x, v.y), pack_bf16(v.z, v.w));
}

__global__ void rank_kernel(const float* __restrict__ sal, int* __restrict__ idx) {
    __shared__ float tile[256];
    int b = blockIdx.y;
    int i = blockIdx.x * 256 + threadIdx.x;
    float v = (i < NTOK) ? sal[b * NTOK + i] : 0.0f;
    int rank = 0;
    const int NT = (NTOK + 255) / 256;
    for (int t = 0; t < NT; t++) {
        int j = t * 256 + threadIdx.x;
        tile[threadIdx.x] = (j < NTOK) ? sal[b * NTOK + j] : -3.402823466e38f;
        __syncthreads();
        int base = t * 256;
#pragma unroll 8
        for (int jj = 0; jj < 256; jj++) {
            float w = tile[jj];
            rank += (w > v) || (w == v && (base + jj) < i);
        }
        __syncthreads();
    }
    if (i < NTOK) idx[b * NTOK + rank] = i;
}

// final scatter: rank-ordered px -> feature bank (all KMAX ranks, both batches)
__global__ void fscatter_kernel(const float* __restrict__ px, const int* __restrict__ idx,
                                float* __restrict__ out) {
    int row = blockIdx.x * 8 + (threadIdx.x >> 5);
    if (row >= NB * KMAX) return;
    int lane = threadIdx.x & 31;
    int b = (row >= KMAX) ? 1 : 0;
    int rank = row - b * KMAX;
    int dst = idx[b * NTOK + rank];
    const float* sp = px + (size_t)row * DM + lane * 8;
    float* dp = out + ((size_t)b * NTOK + dst) * DM + lane * 8;
    float4 v0 = *(const float4*)sp;
    float4 v1 = *(const float4*)(sp + 4);
    *(float4*)dp = v0;
    *(float4*)(dp + 4) = v1;
}

// ---------------- warp-per-2-tokens LayerNorm (bf16 h output, rank space) ----------------
// Each warp handles 2 rows; all 4 global loads issued up front for MLP.
template <int GATHER>
__global__ void lnw_kernel(const float* __restrict__ src, const int* __restrict__ idx,
                           const float* __restrict__ gam, const float* __restrict__ bet,
                           float* __restrict__ px, __nv_bfloat16* __restrict__ h, int kc, int M) {
    int warp = threadIdx.x >> 5, lane = threadIdx.x & 31;
    int rowA = blockIdx.x * 16 + warp * 2;
    int rowB = rowA + 1;
    if (rowA >= M) return;
    bool vB = rowB < M;
    int rmA = row_map(rowA, kc);
    int rmB = row_map(rowB, kc);
    const float *pA, *pB;
    if (GATHER) {
        int bA = (rowA >= kc) ? 1 : 0;
        int bB = (rowB >= kc) ? 1 : 0;
        int srA = idx[bA * NTOK + (rowA - bA * kc)];
        int srB = vB ? idx[bB * NTOK + (rowB - bB * kc)] : srA;
        pA = src + ((size_t)bA * NTOK + srA) * DM + lane * 8;
        pB = src + ((size_t)bB * NTOK + srB) * DM + lane * 8;
    } else {
        pA = src + (size_t)rmA * DM + lane * 8;
        pB = src + (size_t)rmB * DM + lane * 8;
    }
    float4 a0 = *(const float4*)pA;
    float4 a1 = *(const float4*)(pA + 4);
    float4 b0, b1;
    if (vB) { b0 = *(const float4*)pB; b1 = *(const float4*)(pB + 4); }
    float4 gg0 = *(const float4*)(gam + lane * 8);
    float4 gg1 = *(const float4*)(gam + lane * 8 + 4);
    float4 bb0 = *(const float4*)(bet + lane * 8);
    float4 bb1 = *(const float4*)(bet + lane * 8 + 4);

    if (GATHER) {
        float* xp = px + (size_t)rmA * DM + lane * 8;
        *(float4*)xp = a0;
        *(float4*)(xp + 4) = a1;
        if (vB) {
            float* xq = px + (size_t)rmB * DM + lane * 8;
            *(float4*)xq = b0;
            *(float4*)(xq + 4) = b1;
        }
    }

    // row A
    {
        float s = a0.x + a0.y + a0.z + a0.w + a1.x + a1.y + a1.z + a1.w;
#pragma unroll
        for (int o = 16; o; o >>= 1) s += __shfl_xor_sync(0xffffffffu, s, o);
        float mu = s * (1.0f / DM);
        float c[8] = {a0.x - mu, a0.y - mu, a0.z - mu, a0.w - mu,
                      a1.x - mu, a1.y - mu, a1.z - mu, a1.w - mu};
        float vs = 0.f;
#pragma unroll
        for (int j = 0; j < 8; j++) vs = fmaf(c[j], c[j], vs);
#pragma unroll
        for (int o = 16; o; o >>= 1) vs += __shfl_xor_sync(0xffffffffu, vs, o);
        float inv = rsqrtf(vs * (1.0f / DM) + 1e-5f);
        uint4 o4;
        o4.x = pack_bf16(fmaf(c[0] * inv, gg0.x, bb0.x), fmaf(c[1] * inv, gg0.y, bb0.y));
        o4.y = pack_bf16(fmaf(c[2] * inv, gg0.z, bb0.z), fmaf(c[3] * inv, gg0.w, bb0.w));
        o4.z = pack_bf16(fmaf(c[4] * inv, gg1.x, bb1.x), fmaf(c[5] * inv, gg1.y, bb1.y));
        o4.w = pack_bf16(fmaf(c[6] * inv, gg1.z, bb1.z), fmaf(c[7] * inv, gg1.w, bb1.w));
        *(uint4*)(h + (size_t)rmA * DM + lane * 8) = o4;
    }
    // row B
    if (vB) {
        float s = b0.x + b0.y + b0.z + b0.w + b1.x + b1.y + b1.z + b1.w;
#pragma unroll
        for (int o = 16; o; o >>= 1) s += __shfl_xor_sync(0xffffffffu, s, o);
        float mu = s * (1.0f / DM);
        float c[8] = {b0.x - mu, b0.y - mu, b0.z - mu, b0.w - mu,
                      b1.x - mu, b1.y - mu, b1.z - mu, b1.w - mu};
        float vs = 0.f;
#pragma unroll
        for (int j = 0; j < 8; j++) vs = fmaf(c[j], c[j], vs);
#pragma unroll
        for (int o = 16; o; o >>= 1) vs += __shfl_xor_sync(0xffffffffu, vs, o);
        float inv = rsqrtf(vs * (1.0f / DM) + 1e-5f);
        uint4 o4;
        o4.x = pack_bf16(fmaf(c[0] * inv, gg0.x, bb0.x), fmaf(c[1] * inv, gg0.y, bb0.y));
        o4.y = pack_bf16(fmaf(c[2] * inv, gg0.z, bb0.z), fmaf(c[3] * inv, gg0.w, bb0.w));
        o4.z = pack_bf16(fmaf(c[4] * inv, gg1.x, bb1.x), fmaf(c[5] * inv, gg1.y, bb1.y));
        o4.w = pack_bf16(fmaf(c[6] * inv, gg1.z, bb1.z), fmaf(c[7] * inv, gg1.w, bb1.w));
        *(uint4*)(h + (size_t)rmB * DM + lane * 8) = o4;
    }
}

// ---------------- bf16 ldmatrix GEMM, 3-stage cp.async pipeline ----------------
struct BGemmCtx {
    uint32_t a_base, b_base;
    int arow, akq, brow, bnc;
    int a_row_off, a_kh;
    int wm, wn;
};

#define A_STAGE_B (128 * 40 * 2)
#define B_STAGE_B (32 * 72 * 2)

__device__ __forceinline__ BGemmCtx make_ctx(void* As, void* Bs) {
    int tid = threadIdx.x;
    int warp = tid >> 5, lane = tid & 31;
    BGemmCtx c;
    c.a_base = (uint32_t)__cvta_generic_to_shared(As);
    c.b_base = (uint32_t)__cvta_generic_to_shared(Bs);
    c.arow = tid >> 1;
    c.akq = (tid & 1) * 16;
    c.brow = tid >> 3;
    c.bnc = (tid & 7) * 8;
    c.a_row_off = (lane & 7) + ((lane >> 3) & 1) * 8;
    c.a_kh = (lane >> 4) * 8;
    c.wm = (warp & 3) * 32;
    c.wn = (warp >> 2) * 32;
    return c;
}

template <int MAPA>
__device__ __forceinline__ void bgemm_stage_load(
    const __nv_bfloat16* __restrict__ A, const __nv_bfloat16* __restrict__ W,
    int M, int N, int K, int m0, int n0, const BGemmCtx& c, int s, int nit, int kc) {
    if (s < nit) {
        int sb = s % 3;
        int k0 = s << 5;
        int gr = m0 + c.arow;
        bool pr = gr < M;
        int grm = MAPA ? row_map(gr, kc) : gr;
        cp16(c.a_base + sb * A_STAGE_B + (c.arow * 40 + c.akq) * 2,
             A + (size_t)grm * K + k0 + c.akq, pr);
        cp16(c.a_base + sb * A_STAGE_B + (c.arow * 40 + c.akq + 8) * 2,
             A + (size_t)grm * K + k0 + c.akq + 8, pr);
        cp16(c.b_base + sb * B_STAGE_B + (c.brow * 72 + c.bnc) * 2,
             W + (size_t)(k0 + c.brow) * N + n0 + c.bnc, true);
    }
    CP_COMMIT();
}

template <int MAPA>
__device__ __forceinline__ void bgemm_mainloop(
    const __nv_bfloat16* __restrict__ A, const __nv_bfloat16* __restrict__ W,
    int M, int N, int K, int m0, int n0, const BGemmCtx& c, float acc[2][4][4], int kc) {
    int nit = K >> 5;
    bgemm_stage_load<MAPA>(A, W, M, N, K, m0, n0, c, 0, nit, kc);
    bgemm_stage_load<MAPA>(A, W, M, N, K, m0, n0, c, 1, nit, kc);
    for (int it = 0; it < nit; it++) {
        CP_WAIT1();
        __syncthreads();
        bgemm_stage_load<MAPA>(A, W, M, N, K, m0, n0, c, it + 2, nit, kc);
        int sb = it % 3;
        uint32_t ab = c.a_base + sb * A_STAGE_B;
        uint32_t bb = c.b_base + sb * B_STAGE_B;
#pragma unroll
        for (int ks = 0; ks < 2; ks++) {
            uint32_t af[2][4], bf[2][4];
#pragma unroll
            for (int mt = 0; mt < 2; mt++)
                ldsm_x4(af[mt], ab + ((c.wm + mt * 16 + c.a_row_off) * 40 + ks * 16 + c.a_kh) * 2);
#pragma unroll
            for (int nb = 0; nb < 2; nb++)
                ldsm_x4t(bf[nb], bb + ((ks * 16 + c.a_row_off) * 72 + c.wn + nb * 16 + c.a_kh) * 2);
#pragma unroll
            for (int mt = 0; mt < 2; mt++)
#pragma unroll
                for (int n8 = 0; n8 < 4; n8++)
                    mma_bf16(acc[mt][n8], af[mt], bf[n8 >> 1][(n8 & 1) * 2], bf[n8 >> 1][(n8 & 1) * 2 + 1]);
        }
    }
}

// EPI: 1 = f32 residual add into Outv (row-mapped if MAPC), 2 = gelu -> bf16 Outv (dense)
template <int EPI, int MAPA, int MAPC>
__global__ void __launch_bounds__(256)
bgemm_kernel(const __nv_bfloat16* __restrict__ A, const __nv_bfloat16* __restrict__ W,
             void* __restrict__ Outv, int M, int N, int K, int kc) {
    __shared__ __nv_bfloat16 As[3][128][40];
    __shared__ __nv_bfloat16 Bs[3][32][72];
    int m0 = blockIdx.x * 128, n0 = blockIdx.y * 64;
    BGemmCtx c = make_ctx(As, Bs);
    float acc[2][4][4] = {};
    bgemm_mainloop<MAPA>(A, W, M, N, K, m0, n0, c, acc, kc);

    int lane = threadIdx.x & 31, g = lane >> 2, tg = lane & 3;
#pragma unroll
    for (int mt = 0; mt < 2; mt++) {
#pragma unroll
        for (int half = 0; half < 2; half++) {
            int r = m0 + c.wm + mt * 16 + g + half * 8;
            if (r >= M) continue;
            int rc = MAPC ? row_map(r, kc) : r;
#pragma unroll
            for (int n8 = 0; n8 < 4; n8++) {
                int col = n0 + c.wn + n8 * 8 + 2 * tg;
                float c0 = acc[mt][n8][half * 2 + 0];
                float c1 = acc[mt][n8][half * 2 + 1];
                if (EPI == 1) {
                    float* cp = (float*)Outv + (size_t)rc * N + col;
                    float2 o = *(float2*)cp;
                    o.x += c0; o.y += c1;
                    *(float2*)cp = o;
                } else {  // EPI == 2
                    *(uint32_t*)((__nv_bfloat16*)Outv + (size_t)rc * N + col) =
                        pack_bf16(gelu_f(c0), gelu_f(c1));
                }
            }
        }
    }
}

__global__ void __launch_bounds__(256)
qkvb_kernel(const __nv_bfloat16* __restrict__ A,
            const __nv_bfloat16* __restrict__ Wq, const __nv_bfloat16* __restrict__ Wk,
            const __nv_bfloat16* __restrict__ Wv,
            __nv_bfloat16* __restrict__ Oq, __nv_bfloat16* __restrict__ Ok,
            __nv_bfloat16* __restrict__ Ov, int M, int kc, float qscale) {
    __shared__ __nv_bfloat16 As[3][128][40];
    __shared__ __nv_bfloat16 Bs[3][32][72];
    int which = blockIdx.y >> 2;
    int n0 = (blockIdx.y & 3) * 64;
    int m0 = blockIdx.x * 128;
    const __nv_bfloat16* W = (which == 0) ? Wq : ((which == 1) ? Wk : Wv);
    __nv_bfloat16* Ob = (which == 0) ? Oq : ((which == 1) ? Ok : Ov);
    float sc = (which == 0) ? qscale : 1.0f;
    BGemmCtx c = make_ctx(As, Bs);
    float acc[2][4][4] = {};
    bgemm_mainloop<1>(A, W, M, DM, DM, m0, n0, c, acc, kc);  // A = h (rank-mapped)

    int lane = threadIdx.x & 31, g = lane >> 2, tg = lane & 3;
#pragma unroll
    for (int mt = 0; mt < 2; mt++) {
#pragma unroll
        for (int half = 0; half < 2; half++) {
            int r = m0 + c.wm + mt * 16 + g + half * 8;
            if (r >= M) continue;
#pragma unroll
            for (int n8 = 0; n8 < 4; n8++) {
                int col = n0 + c.wn + n8 * 8 + 2 * tg;
                *(uint32_t*)(Ob + (size_t)r * DM + col) =
                    pack_bf16(acc[mt][n8][half * 2 + 0] * sc, acc[mt][n8][half * 2 + 1] * sc);
            }
        }
    }
}

// ---------------- flash attention: q-tile 128, 64-key 3-stage cp.async (R11 config) ----------------
__global__ void __launch_bounds__(256) attn_mma_kernel(const __nv_bfloat16* __restrict__ Q,
                                                       const __nv_bfloat16* __restrict__ Kx,
                                                       const __nv_bfloat16* __restrict__ Vx,
                                                       __nv_bfloat16* __restrict__ O, int kc) {
    __shared__ __nv_bfloat16 Ks[3][64][40];
    __shared__ __nv_bfloat16 Vs[3][64][40];
    const int TILE_B = 64 * 40 * 2;
    int b = blockIdx.z, hh = blockIdx.y;
    int q0 = blockIdx.x * 128;
    int tid = threadIdx.x;
    int warp = tid >> 5, lane = tid & 31, g = lane >> 2, tg = lane & 3;
    const __nv_bfloat16* Qp = Q + ((size_t)b * kc) * DM + hh * DH;
    const __nv_bfloat16* Kp = Kx + ((size_t)b * kc) * DM + hh * DH;
    const __nv_bfloat16* Vg = Vx + ((size_t)b * kc) * DM + hh * DH;

    uint32_t ksb = (uint32_t)__cvta_generic_to_shared(Ks);
    uint32_t vsb = (uint32_t)__cvta_generic_to_shared(Vs);
    int lrow = tid >> 2;
    int lch  = (tid & 3) * 8;
    int aro  = lane & 15;
    int akh  = (lane >> 4) * 8;

    // stage Q tile (rows 0-63 -> Ks[0], 64-127 -> Vs[0]) via cp.async
    {
        int gq0 = q0 + lrow, gq1 = q0 + 64 + lrow;
        cp16(ksb + (lrow * 40 + lch) * 2, Qp + (size_t)gq0 * DM + lch, gq0 < kc);
        cp16(vsb + (lrow * 40 + lch) * 2, Qp + (size_t)gq1 * DM + lch, gq1 < kc);
    }
    CP_COMMIT();
    CP_WAIT0();
    __syncthreads();
    uint32_t qf[2][4];
    {
        int wq = warp * 16;
        uint32_t qsm = (wq < 64) ? ksb : vsb;
        int wql = wq & 63;
        ldsm_x4(qf[0], qsm + ((wql + aro) * 40 + akh) * 2);
        ldsm_x4(qf[1], qsm + ((wql + aro) * 40 + 16 + akh) * 2);
    }
    __syncthreads();

    float oacc[4][4] = {};
    float lsum[2] = {0.f, 0.f};
    int ntile = (kc + 63) >> 6;

#pragma unroll
    for (int s = 0; s < 2; s++) {
        if (s < ntile) {
            int gk = s * 64 + lrow;
            bool pr = gk < kc;
            cp16(ksb + s * TILE_B + (lrow * 40 + lch) * 2, Kp + (size_t)gk * DM + lch, pr);
            cp16(vsb + s * TILE_B + (lrow * 40 + lch) * 2, Vg + (size_t)gk * DM + lch, pr);
        }
        CP_COMMIT();
    }

    for (int kt = 0; kt < ntile; kt++) {
        CP_WAIT1();
        __syncthreads();
        {
            int s = kt + 2;
            if (s < ntile) {
                int sb = s % 3;
                int gk = s * 64 + lrow;
                bool pr = gk < kc;
                cp16(ksb + sb * TILE_B + (lrow * 40 + lch) * 2, Kp + (size_t)gk * DM + lch, pr);
                cp16(vsb + sb * TILE_B + (lrow * 40 + lch) * 2, Vg + (size_t)gk * DM + lch, pr);
            }
            CP_COMMIT();
        }
        int sb = kt % 3;
        uint32_t kb_ = ksb + sb * TILE_B;
        uint32_t vb_ = vsb + sb * TILE_B;
        int j0 = kt << 6;

        float sacc[8][4] = {};
#pragma unroll
        for (int ks = 0; ks < 2; ks++) {
#pragma unroll
            for (int i = 0; i < 4; i++) {
                uint32_t br[4];
                ldsm_x4(br, kb_ + ((i * 16 + aro) * 40 + ks * 16 + akh) * 2);
                mma_bf16(sacc[2 * i],     qf[ks], br[0], br[2]);
                mma_bf16(sacc[2 * i + 1], qf[ks], br[1], br[3]);
            }
        }
        if (j0 + 64 > kc) {
#pragma unroll
            for (int jn = 0; jn < 8; jn++)
                if (j0 + 8 * jn >= kc) {
                    sacc[jn][0] = -1e30f; sacc[jn][1] = -1e30f;
                    sacc[jn][2] = -1e30f; sacc[jn][3] = -1e30f;
                }
        }
#pragma unroll
        for (int jn = 0; jn < 8; jn++) {
            float p0 = mufu_ex2(sacc[jn][0]);
            float p1 = mufu_ex2(sacc[jn][1]);
            float p2 = mufu_ex2(sacc[jn][2]);
            float p3 = mufu_ex2(sacc[jn][3]);
            sacc[jn][0] = p0; sacc[jn][1] = p1; sacc[jn][2] = p2; sacc[jn][3] = p3;
            lsum[0] += p0 + p1;
            lsum[1] += p2 + p3;
        }
#pragma unroll
        for (int s = 0; s < 4; s++) {
            uint32_t pf[4];
            pf[0] = pack_bf16(sacc[2 * s][0], sacc[2 * s][1]);
            pf[1] = pack_bf16(sacc[2 * s][2], sacc[2 * s][3]);
            pf[2] = pack_bf16(sacc[2 * s + 1][0], sacc[2 * s + 1][1]);
            pf[3] = pack_bf16(sacc[2 * s + 1][2], sacc[2 * s + 1][3]);
#pragma unroll
            for (int dv = 0; dv < 2; dv++) {
                uint32_t br[4];
                ldsm_x4t(br, vb_ + ((s * 16 + aro) * 40 + dv * 16 + akh) * 2);
                mma_bf16(oacc[2 * dv],     pf, br[0], br[1]);
                mma_bf16(oacc[2 * dv + 1], pf, br[2], br[3]);
            }
        }
    }

    lsum[0] += __shfl_xor_sync(0xffffffffu, lsum[0], 1);
    lsum[0] += __shfl_xor_sync(0xffffffffu, lsum[0], 2);
    lsum[1] += __shfl_xor_sync(0xffffffffu, lsum[1], 1);
    lsum[1] += __shfl_xor_sync(0xffffffffu, lsum[1], 2);
    float inv0 = __fdividef(1.0f, lsum[0]);
    float inv1 = __fdividef(1.0f, lsum[1]);

    int qr0 = q0 + warp * 16 + g;
    int qr1 = qr0 + 8;
    if (qr0 < kc) {
        __nv_bfloat16* op = O + ((size_t)b * kc + qr0) * DM + hh * DH;
#pragma unroll
        for (int dn = 0; dn < 4; dn++)
            *(uint32_t*)(op + 8 * dn + 2 * tg) = pack_bf16(oacc[dn][0] * inv0, oacc[dn][1] * inv0);
    }
    if (qr1 < kc) {
        __nv_bfloat16* op = O + ((size_t)b * kc + qr1) * DM + hh * DH;
#pragma unroll
        for (int dn = 0; dn < 4; dn++)
            *(uint32_t*)(op + 8 * dn + 2 * tg) = pack_bf16(oacc[dn][2] * inv1, oacc[dn][3] * inv1);
    }
}

// ---------------- launch ----------------
extern "C" void kernel_launch(void* const* d_in, const int* in_sizes, int n_in,
                              void* d_out, int out_size) {
    const float* feat = (const float*)d_in[0];
    const float* sal  = (const float*)d_in[1];
    const float* Wq   = (const float*)d_in[2];
    const float* Wk   = (const float*)d_in[3];
    const float* Wv   = (const float*)d_in[4];
    const float* Wo   = (const float*)d_in[5];
    const float* W1   = (const float*)d_in[6];
    const float* W2   = (const float*)d_in[7];
    const float* g1   = (const float*)d_in[8];
    const float* b1   = (const float*)d_in[9];
    const float* g2   = (const float*)d_in[10];
    const float* b2   = (const float*)d_in[11];
    float* out = (float*)d_out;

    float *px, *ph, *pq, *pk, *pv, *pa, *pf;
    __nv_bfloat16* pwb;
    int* pidx;
    cudaGetSymbolAddress((void**)&px, g_x);
    cudaGetSymbolAddress((void**)&ph, g_h);
    cudaGetSymbolAddress((void**)&pq, g_q);
    cudaGetSymbolAddress((void**)&pk, g_k);
    cudaGetSymbolAddress((void**)&pv, g_v);
    cudaGetSymbolAddress((void**)&pa, g_a);
    cudaGetSymbolAddress((void**)&pf, g_f);
    cudaGetSymbolAddress((void**)&pwb, g_wb);
    cudaGetSymbolAddress((void**)&pidx, g_idx);

    __nv_bfloat16* hb = (__nv_bfloat16*)ph;
    __nv_bfloat16* qb = (__nv_bfloat16*)pq;
    __nv_bfloat16* kb = (__nv_bfloat16*)pk;
    __nv_bfloat16* vb = (__nv_bfloat16*)pv;
    __nv_bfloat16* ab = (__nv_bfloat16*)pa;
    __nv_bfloat16* fb = (__nv_bfloat16*)pf;

    // 1/sqrt(32) * log2(e): softmax done in exp2 domain
    const float qscale = 0.17677669529663687f * 1.4426950408889634f;
    const int n4 = NB * NTOK * DM / 4;
    copy_kernel<<<(n4 + 255) / 256, 256>>>((const float4*)feat, (float4*)out, n4);
    rank_kernel<<<dim3((NTOK + 255) / 256, NB), 256>>>(sal, pidx);
    cvtw_kernel<<<WB_TOTAL / 4 / 256, 256>>>((const float4*)Wq, (const float4*)Wk,
                                             (const float4*)Wv, (const float4*)Wo,
                                             (const float4*)W1, (const float4*)W2, (uint2*)pwb);

    static const int KCNT[4] = {3200, 2400, 2000, 1600};
    for (int l = 0; l < 4; l++) {
        int kc = KCNT[l];
        int M = NB * kc;
        int gx128 = (M + 127) / 128;
        const __nv_bfloat16* wq_l = pwb + (size_t)l * 65536;
        const __nv_bfloat16* wk_l = pwb + WK_OFF + (size_t)l * 65536;
        const __nv_bfloat16* wv_l = pwb + WV_OFF + (size_t)l * 65536;
        const __nv_bfloat16* wo_l = pwb + WO_OFF + (size_t)l * 65536;
        const __nv_bfloat16* w1_l = pwb + W1_OFF + (size_t)l * 262144;
        const __nv_bfloat16* w2_l = pwb + W2_OFF + (size_t)l * 262144;

        if (l == 0)
            lnw_kernel<1><<<(M + 15) / 16, 256>>>(out, pidx, g1, b1, px, hb, kc, M);
        else
            lnw_kernel<0><<<(M + 15) / 16, 256>>>(px, nullptr, g1 + l * DM, b1 + l * DM, nullptr, hb, kc, M);
        qkvb_kernel<<<dim3(gx128, 12), 256>>>(hb, wq_l, wk_l, wv_l, qb, kb, vb, M, kc, qscale);
        attn_mma_kernel<<<dim3((kc + 127) / 128, NH, NB), 256>>>(qb, kb, vb, ab, kc);
        bgemm_kernel<1, 0, 1><<<dim3(gx128, 4), 256>>>(ab, wo_l, px, M, DM, DM, kc);
        lnw_kernel<0><<<(M + 15) / 16, 256>>>(px, nullptr, g2 + l * DM, b2 + l * DM, nullptr, hb, kc, M);
        bgemm_kernel<2, 1, 0><<<dim3(gx128, 16), 256>>>(hb, w1_l, fb, M, 4 * DM, DM, kc);
        bgemm_kernel<1, 0, 1><<<dim3(gx128, 4), 256>>>(fb, w2_l, px, M, DM, 4 * DM, kc);
    }
    fscatter_kernel<<<(NB * KMAX + 7) / 8, 256>>>(px, pidx, out);
}

// round 16
// speedup vs baseline: 1.0339x; 1.0205x over previous
#include <cuda_runtime.h>
#include <cuda_bf16.h>
#include <cstdint>

#define NB   2
#define NTOK 8000
#define DM   256
#define NH   8
#define DH   32
#define KMAX 3200

#define WK_OFF 262144
#define WV_OFF 524288
#define WO_OFF 786432
#define W1_OFF 1048576
#define W2_OFF 2097152
#define WB_TOTAL 3145728

// ---------------- scratch (device globals; no allocations) ----------------
__device__ float g_x[NB * KMAX * DM];
__device__ float g_h[NB * KMAX * DM];          // bf16 h (rank-ordered)
__device__ float g_q[NB * KMAX * DM];
__device__ float g_k[NB * KMAX * DM];
__device__ float g_v[NB * KMAX * DM];
__device__ float g_a[NB * KMAX * DM];
__device__ float g_f[NB * KMAX * 4 * DM];
__device__ __nv_bfloat16 g_wb[WB_TOTAL];
__device__ int   g_idx[NB * NTOK];

// ---------------- fast math helpers ----------------
__device__ __forceinline__ float mufu_ex2(float z) {
    float r; asm("ex2.approx.ftz.f32 %0, %1;" : "=f"(r) : "f"(z)); return r;
}
__device__ __forceinline__ float mufu_rcp(float z) {
    float r; asm("rcp.approx.ftz.f32 %0, %1;" : "=f"(r) : "f"(z)); return r;
}
__device__ __forceinline__ float gelu_f(float x) {
    float u = 1.5957691216057308f * fmaf(0.044715f * x * x, x, x);
    return x * mufu_rcp(1.0f + mufu_ex2(u * -1.4426950408889634f));
}
__device__ __forceinline__ uint32_t pack_bf16(float lo, float hi) {
    uint32_t d; asm("cvt.rn.bf16x2.f32 %0, %1, %2;" : "=r"(d) : "f"(hi), "f"(lo)); return d;
}
__device__ __forceinline__ void mma_bf16(float* d, const uint32_t* a, uint32_t b0, uint32_t b1) {
    asm volatile(
        "mma.sync.aligned.m16n8k16.row.col.f32.bf16.bf16.f32 "
        "{%0,%1,%2,%3}, {%4,%5,%6,%7}, {%8,%9}, {%0,%1,%2,%3};"
        : "+f"(d[0]), "+f"(d[1]), "+f"(d[2]), "+f"(d[3])
        : "r"(a[0]), "r"(a[1]), "r"(a[2]), "r"(a[3]), "r"(b0), "r"(b1));
}
__device__ __forceinline__ void ldsm_x4(uint32_t* r, uint32_t addr) {
    asm volatile("ldmatrix.sync.aligned.m8n8.x4.shared.b16 {%0,%1,%2,%3}, [%4];"
                 : "=r"(r[0]), "=r"(r[1]), "=r"(r[2]), "=r"(r[3]) : "r"(addr));
}
__device__ __forceinline__ void ldsm_x4t(uint32_t* r, uint32_t addr) {
    asm volatile("ldmatrix.sync.aligned.m8n8.x4.trans.shared.b16 {%0,%1,%2,%3}, [%4];"
                 : "=r"(r[0]), "=r"(r[1]), "=r"(r[2]), "=r"(r[3]) : "r"(addr));
}
__device__ __forceinline__ void cp16(uint32_t dst, const void* src, bool pred) {
    int sz = pred ? 16 : 0;
    asm volatile("cp.async.cg.shared.global [%0], [%1], 16, %2;" :: "r"(dst), "l"(src), "r"(sz));
}
#define CP_COMMIT() asm volatile("cp.async.commit_group;")
#define CP_WAIT0()  asm volatile("cp.async.wait_group 0;")
#define CP_WAIT1()  asm volatile("cp.async.wait_group 1;")

__device__ __forceinline__ int row_map(int r, int kc) {
    return r + ((r >= kc) ? (KMAX - kc) : 0);
}

// ---------------- utility kernels ----------------
__global__ void copy_kernel(const float4* __restrict__ in, float4* __restrict__ out, int n4) {
    int i = blockIdx.x * blockDim.x + threadIdx.x;
    if (i < n4) out[i] = in[i];
}

__global__ void cvtw_kernel(const float4* __restrict__ wq, const float4* __restrict__ wk,
                            const float4* __restrict__ wv, const float4* __restrict__ wo,
                            const float4* __restrict__ w1, const float4* __restrict__ w2,
                            uint2* __restrict__ dst) {
    int i = blockIdx.x * 256 + threadIdx.x;
    const float4* src;
    int off;
    if (i < 65536)        { src = wq; off = i; }
    else if (i < 131072)  { src = wk; off = i - 65536; }
    else if (i < 196608)  { src = wv; off = i - 131072; }
    else if (i < 262144)  { src = wo; off = i - 196608; }
    else if (i < 524288)  { src = w1; off = i - 262144; }
    else                  { src = w2; off = i - 524288; }
    float4 v = src[off];
    dst[i] = make_uint2(pack_bf16(v.x, v.y), pack_bf16(v.z, v.w));
}

__global__ void rank_kernel(const float* __restrict__ sal, int* __restrict__ idx) {
    __shared__ float tile[256];
    int b = blockIdx.y;
    int i = blockIdx.x * 256 + threadIdx.x;
    float v = (i < NTOK) ? sal[b * NTOK + i] : 0.0f;
    int rank = 0;
    const int NT = (NTOK + 255) / 256;
    for (int t = 0; t < NT; t++) {
        int j = t * 256 + threadIdx.x;
        tile[threadIdx.x] = (j < NTOK) ? sal[b * NTOK + j] : -3.402823466e38f;
        __syncthreads();
        int base = t * 256;
#pragma unroll 8
        for (int jj = 0; jj < 256; jj++) {
            float w = tile[jj];
            rank += (w > v) || (w == v && (base + jj) < i);
        }
        __syncthreads();
    }
    if (i < NTOK) idx[b * NTOK + rank] = i;
}

__global__ void fscatter_kernel(const float* __restrict__ px, const int* __restrict__ idx,
                                float* __restrict__ out) {
    int row = blockIdx.x * 8 + (threadIdx.x >> 5);
    if (row >= NB * KMAX) return;
    int lane = threadIdx.x & 31;
    int b = (row >= KMAX) ? 1 : 0;
    int rank = row - b * KMAX;
    int dst = idx[b * NTOK + rank];
    const float* sp = px + (size_t)row * DM + lane * 8;
    float* dp = out + ((size_t)b * NTOK + dst) * DM + lane * 8;
    float4 v0 = *(const float4*)sp;
    float4 v1 = *(const float4*)(sp + 4);
    *(float4*)dp = v0;
    *(float4*)(dp + 4) = v1;
}

// ---------------- warp-per-2-tokens LayerNorm (R14) ----------------
template <int GATHER>
__global__ void lnw_kernel(const float* __restrict__ src, const int* __restrict__ idx,
                           const float* __restrict__ gam, const float* __restrict__ bet,
                           float* __restrict__ px, __nv_bfloat16* __restrict__ h, int kc, int M) {
    int warp = threadIdx.x >> 5, lane = threadIdx.x & 31;
    int rowA = blockIdx.x * 16 + warp * 2;
    int rowB = rowA + 1;
    if (rowA >= M) return;
    bool vB = rowB < M;
    int rmA = row_map(rowA, kc);
    int rmB = row_map(rowB, kc);
    const float *pA, *pB;
    if (GATHER) {
        int bA = (rowA >= kc) ? 1 : 0;
        int bB = (rowB >= kc) ? 1 : 0;
        int srA = idx[bA * NTOK + (rowA - bA * kc)];
        int srB = vB ? idx[bB * NTOK + (rowB - bB * kc)] : srA;
        pA = src + ((size_t)bA * NTOK + srA) * DM + lane * 8;
        pB = src + ((size_t)bB * NTOK + srB) * DM + lane * 8;
    } else {
        pA = src + (size_t)rmA * DM + lane * 8;
        pB = src + (size_t)rmB * DM + lane * 8;
    }
    float4 a0 = *(const float4*)pA;
    float4 a1 = *(const float4*)(pA + 4);
    float4 b0, b1;
    if (vB) { b0 = *(const float4*)pB; b1 = *(const float4*)(pB + 4); }
    float4 gg0 = *(const float4*)(gam + lane * 8);
    float4 gg1 = *(const float4*)(gam + lane * 8 + 4);
    float4 bb0 = *(const float4*)(bet + lane * 8);
    float4 bb1 = *(const float4*)(bet + lane * 8 + 4);

    if (GATHER) {
        float* xp = px + (size_t)rmA * DM + lane * 8;
        *(float4*)xp = a0;
        *(float4*)(xp + 4) = a1;
        if (vB) {
            float* xq = px + (size_t)rmB * DM + lane * 8;
            *(float4*)xq = b0;
            *(float4*)(xq + 4) = b1;
        }
    }
    {
        float s = a0.x + a0.y + a0.z + a0.w + a1.x + a1.y + a1.z + a1.w;
#pragma unroll
        for (int o = 16; o; o >>= 1) s += __shfl_xor_sync(0xffffffffu, s, o);
        float mu = s * (1.0f / DM);
        float c[8] = {a0.x - mu, a0.y - mu, a0.z - mu, a0.w - mu,
                      a1.x - mu, a1.y - mu, a1.z - mu, a1.w - mu};
        float vs = 0.f;
#pragma unroll
        for (int j = 0; j < 8; j++) vs = fmaf(c[j], c[j], vs);
#pragma unroll
        for (int o = 16; o; o >>= 1) vs += __shfl_xor_sync(0xffffffffu, vs, o);
        float inv = rsqrtf(vs * (1.0f / DM) + 1e-5f);
        uint4 o4;
        o4.x = pack_bf16(fmaf(c[0] * inv, gg0.x, bb0.x), fmaf(c[1] * inv, gg0.y, bb0.y));
        o4.y = pack_bf16(fmaf(c[2] * inv, gg0.z, bb0.z), fmaf(c[3] * inv, gg0.w, bb0.w));
        o4.z = pack_bf16(fmaf(c[4] * inv, gg1.x, bb1.x), fmaf(c[5] * inv, gg1.y, bb1.y));
        o4.w = pack_bf16(fmaf(c[6] * inv, gg1.z, bb1.z), fmaf(c[7] * inv, gg1.w, bb1.w));
        *(uint4*)(h + (size_t)rmA * DM + lane * 8) = o4;
    }
    if (vB) {
        float s = b0.x + b0.y + b0.z + b0.w + b1.x + b1.y + b1.z + b1.w;
#pragma unroll
        for (int o = 16; o; o >>= 1) s += __shfl_xor_sync(0xffffffffu, s, o);
        float mu = s * (1.0f / DM);
        float c[8] = {b0.x - mu, b0.y - mu, b0.z - mu, b0.w - mu,
                      b1.x - mu, b1.y - mu, b1.z - mu, b1.w - mu};
        float vs = 0.f;
#pragma unroll
        for (int j = 0; j < 8; j++) vs = fmaf(c[j], c[j], vs);
#pragma unroll
        for (int o = 16; o; o >>= 1) vs += __shfl_xor_sync(0xffffffffu, vs, o);
        float inv = rsqrtf(vs * (1.0f / DM) + 1e-5f);
        uint4 o4;
        o4.x = pack_bf16(fmaf(c[0] * inv, gg0.x, bb0.x), fmaf(c[1] * inv, gg0.y, bb0.y));
        o4.y = pack_bf16(fmaf(c[2] * inv, gg0.z, bb0.z), fmaf(c[3] * inv, gg0.w, bb0.w));
        o4.z = pack_bf16(fmaf(c[4] * inv, gg1.x, bb1.x), fmaf(c[5] * inv, gg1.y, bb1.y));
        o4.w = pack_bf16(fmaf(c[6] * inv, gg1.z, bb1.z), fmaf(c[7] * inv, gg1.w, bb1.w));
        *(uint4*)(h + (size_t)rmB * DM + lane * 8) = o4;
    }
}

// ---------------- bf16 ldmatrix GEMM, 3-stage cp.async, BM templated ----------------
// BM=128: 256 thr, 8 warps 4m x 2n.   BM=64: 128 thr, 4 warps 2m x 2n. Warp tile 32x32.
template <int BM>
struct BGemmCtx {
    uint32_t a_base, b_base;
    int arow, akq, brow, bnc;
    int a_row_off, a_kh;
    int wm, wn;
};

#define B_STAGE_B (32 * 72 * 2)

template <int BM>
__device__ __forceinline__ BGemmCtx<BM> make_ctx(void* As, void* Bs) {
    int tid = threadIdx.x;
    int warp = tid >> 5, lane = tid & 31;
    BGemmCtx<BM> c;
    c.a_base = (uint32_t)__cvta_generic_to_shared(As);
    c.b_base = (uint32_t)__cvta_generic_to_shared(Bs);
    c.arow = tid >> 1;
    c.akq = (tid & 1) * 16;
    if (BM == 128) { c.brow = tid >> 3; c.bnc = (tid & 7) * 8; }
    else           { c.brow = tid >> 2; c.bnc = (tid & 3) * 16; }
    c.a_row_off = (lane & 7) + ((lane >> 3) & 1) * 8;
    c.a_kh = (lane >> 4) * 8;
    if (BM == 128) { c.wm = (warp & 3) * 32; c.wn = (warp >> 2) * 32; }
    else           { c.wm = (warp & 1) * 32; c.wn = (warp >> 1) * 32; }
    return c;
}

template <int BM, int MAPA>
__device__ __forceinline__ void bgemm_stage_load(
    const __nv_bfloat16* __restrict__ A, const __nv_bfloat16* __restrict__ W,
    int M, int N, int K, int m0, int n0, const BGemmCtx<BM>& c, int s, int nit, int kc) {
    const int A_ST = BM * 40 * 2;
    if (s < nit) {
        int sb = s % 3;
        int k0 = s << 5;
        int gr = m0 + c.arow;
        bool pr = gr < M;
        int grm = MAPA ? row_map(gr, kc) : gr;
        cp16(c.a_base + sb * A_ST + (c.arow * 40 + c.akq) * 2,
             A + (size_t)grm * K + k0 + c.akq, pr);
        cp16(c.a_base + sb * A_ST + (c.arow * 40 + c.akq + 8) * 2,
             A + (size_t)grm * K + k0 + c.akq + 8, pr);
        cp16(c.b_base + sb * B_STAGE_B + (c.brow * 72 + c.bnc) * 2,
             W + (size_t)(k0 + c.brow) * N + n0 + c.bnc, true);
        if (BM == 64)
            cp16(c.b_base + sb * B_STAGE_B + (c.brow * 72 + c.bnc + 8) * 2,
                 W + (size_t)(k0 + c.brow) * N + n0 + c.bnc + 8, true);
    }
    CP_COMMIT();
}

template <int BM, int MAPA>
__device__ __forceinline__ void bgemm_mainloop(
    const __nv_bfloat16* __restrict__ A, const __nv_bfloat16* __restrict__ W,
    int M, int N, int K, int m0, int n0, const BGemmCtx<BM>& c, float acc[2][4][4], int kc) {
    const int A_ST = BM * 40 * 2;
    int nit = K >> 5;
    bgemm_stage_load<BM, MAPA>(A, W, M, N, K, m0, n0, c, 0, nit, kc);
    bgemm_stage_load<BM, MAPA>(A, W, M, N, K, m0, n0, c, 1, nit, kc);
    for (int it = 0; it < nit; it++) {
        CP_WAIT1();
        __syncthreads();
        bgemm_stage_load<BM, MAPA>(A, W, M, N, K, m0, n0, c, it + 2, nit, kc);
        int sb = it % 3;
        uint32_t ab = c.a_base + sb * A_ST;
        uint32_t bb = c.b_base + sb * B_STAGE_B;
#pragma unroll
        for (int ks = 0; ks < 2; ks++) {
            uint32_t af[2][4], bf[2][4];
#pragma unroll
            for (int mt = 0; mt < 2; mt++)
                ldsm_x4(af[mt], ab + ((c.wm + mt * 16 + c.a_row_off) * 40 + ks * 16 + c.a_kh) * 2);
#pragma unroll
            for (int nb = 0; nb < 2; nb++)
                ldsm_x4t(bf[nb], bb + ((ks * 16 + c.a_row_off) * 72 + c.wn + nb * 16 + c.a_kh) * 2);
#pragma unroll
            for (int mt = 0; mt < 2; mt++)
#pragma unroll
                for (int n8 = 0; n8 < 4; n8++)
                    mma_bf16(acc[mt][n8], af[mt], bf[n8 >> 1][(n8 & 1) * 2], bf[n8 >> 1][(n8 & 1) * 2 + 1]);
        }
    }
}

// EPI: 1 = f32 residual add (row_map if MAPC), 2 = gelu -> bf16 dense
template <int BM, int EPI, int MAPA, int MAPC>
__global__ void __launch_bounds__(BM == 128 ? 256 : 128)
bgemm_kernel(const __nv_bfloat16* __restrict__ A, const __nv_bfloat16* __restrict__ W,
             void* __restrict__ Outv, int M, int N, int K, int kc) {
    __shared__ __nv_bfloat16 As[3][BM][40];
    __shared__ __nv_bfloat16 Bs[3][32][72];
    int m0 = blockIdx.x * BM, n0 = blockIdx.y * 64;
    BGemmCtx<BM> c = make_ctx<BM>(As, Bs);
    float acc[2][4][4] = {};
    bgemm_mainloop<BM, MAPA>(A, W, M, N, K, m0, n0, c, acc, kc);

    int lane = threadIdx.x & 31, g = lane >> 2, tg = lane & 3;
#pragma unroll
    for (int mt = 0; mt < 2; mt++) {
#pragma unroll
        for (int half = 0; half < 2; half++) {
            int r = m0 + c.wm + mt * 16 + g + half * 8;
            if (r >= M) continue;
            int rc = MAPC ? row_map(r, kc) : r;
#pragma unroll
            for (int n8 = 0; n8 < 4; n8++) {
                int col = n0 + c.wn + n8 * 8 + 2 * tg;
                float c0 = acc[mt][n8][half * 2 + 0];
                float c1 = acc[mt][n8][half * 2 + 1];
                if (EPI == 1) {
                    float* cp = (float*)Outv + (size_t)rc * N + col;
                    float2 o = *(float2*)cp;
                    o.x += c0; o.y += c1;
                    *(float2*)cp = o;
                } else {  // EPI == 2
                    *(uint32_t*)((__nv_bfloat16*)Outv + (size_t)rc * N + col) =
                        pack_bf16(gelu_f(c0), gelu_f(c1));
                }
            }
        }
    }
}

__global__ void __launch_bounds__(256)
qkvb_kernel(const __nv_bfloat16* __restrict__ A,
            const __nv_bfloat16* __restrict__ Wq, const __nv_bfloat16* __restrict__ Wk,
            const __nv_bfloat16* __restrict__ Wv,
            __nv_bfloat16* __restrict__ Oq, __nv_bfloat16* __restrict__ Ok,
            __nv_bfloat16* __restrict__ Ov, int M, int kc, float qscale) {
    __shared__ __nv_bfloat16 As[3][128][40];
    __shared__ __nv_bfloat16 Bs[3][32][72];
    int which = blockIdx.y >> 2;
    int n0 = (blockIdx.y & 3) * 64;
    int m0 = blockIdx.x * 128;
    const __nv_bfloat16* W = (which == 0) ? Wq : ((which == 1) ? Wk : Wv);
    __nv_bfloat16* Ob = (which == 0) ? Oq : ((which == 1) ? Ok : Ov);
    float sc = (which == 0) ? qscale : 1.0f;
    BGemmCtx<128> c = make_ctx<128>(As, Bs);
    float acc[2][4][4] = {};
    bgemm_mainloop<128, 1>(A, W, M, DM, DM, m0, n0, c, acc, kc);

    int lane = threadIdx.x & 31, g = lane >> 2, tg = lane & 3;
#pragma unroll
    for (int mt = 0; mt < 2; mt++) {
#pragma unroll
        for (int half = 0; half < 2; half++) {
            int r = m0 + c.wm + mt * 16 + g + half * 8;
            if (r >= M) continue;
#pragma unroll
            for (int n8 = 0; n8 < 4; n8++) {
                int col = n0 + c.wn + n8 * 8 + 2 * tg;
                *(uint32_t*)(Ob + (size_t)r * DM + col) =
                    pack_bf16(acc[mt][n8][half * 2 + 0] * sc, acc[mt][n8][half * 2 + 1] * sc);
            }
        }
    }
}

// ---------------- flash attention (byte-identical to R14 best) ----------------
__global__ void __launch_bounds__(256) attn_mma_kernel(const __nv_bfloat16* __restrict__ Q,
                                                       const __nv_bfloat16* __restrict__ Kx,
                                                       const __nv_bfloat16* __restrict__ Vx,
                                                       __nv_bfloat16* __restrict__ O, int kc) {
    __shared__ __nv_bfloat16 Ks[3][64][40];
    __shared__ __nv_bfloat16 Vs[3][64][40];
    const int TILE_B = 64 * 40 * 2;
    int b = blockIdx.z, hh = blockIdx.y;
    int q0 = blockIdx.x * 128;
    int tid = threadIdx.x;
    int warp = tid >> 5, lane = tid & 31, g = lane >> 2, tg = lane & 3;
    const __nv_bfloat16* Qp = Q + ((size_t)b * kc) * DM + hh * DH;
    const __nv_bfloat16* Kp = Kx + ((size_t)b * kc) * DM + hh * DH;
    const __nv_bfloat16* Vg = Vx + ((size_t)b * kc) * DM + hh * DH;

    uint32_t ksb = (uint32_t)__cvta_generic_to_shared(Ks);
    uint32_t vsb = (uint32_t)__cvta_generic_to_shared(Vs);
    int lrow = tid >> 2;
    int lch  = (tid & 3) * 8;
    int aro  = lane & 15;
    int akh  = (lane >> 4) * 8;

    {
        int gq0 = q0 + lrow, gq1 = q0 + 64 + lrow;
        cp16(ksb + (lrow * 40 + lch) * 2, Qp + (size_t)gq0 * DM + lch, gq0 < kc);
        cp16(vsb + (lrow * 40 + lch) * 2, Qp + (size_t)gq1 * DM + lch, gq1 < kc);
    }
    CP_COMMIT();
    CP_WAIT0();
    __syncthreads();
    uint32_t qf[2][4];
    {
        int wq = warp * 16;
        uint32_t qsm = (wq < 64) ? ksb : vsb;
        int wql = wq & 63;
        ldsm_x4(qf[0], qsm + ((wql + aro) * 40 + akh) * 2);
        ldsm_x4(qf[1], qsm + ((wql + aro) * 40 + 16 + akh) * 2);
    }
    __syncthreads();

    float oacc[4][4] = {};
    float lsum[2] = {0.f, 0.f};
    int ntile = (kc + 63) >> 6;

#pragma unroll
    for (int s = 0; s < 2; s++) {
        if (s < ntile) {
            int gk = s * 64 + lrow;
            bool pr = gk < kc;
            cp16(ksb + s * TILE_B + (lrow * 40 + lch) * 2, Kp + (size_t)gk * DM + lch, pr);
            cp16(vsb + s * TILE_B + (lrow * 40 + lch) * 2, Vg + (size_t)gk * DM + lch, pr);
        }
        CP_COMMIT();
    }

    for (int kt = 0; kt < ntile; kt++) {
        CP_WAIT1();
        __syncthreads();
        {
            int s = kt + 2;
            if (s < ntile) {
                int sb = s % 3;
                int gk = s * 64 + lrow;
                bool pr = gk < kc;
                cp16(ksb + sb * TILE_B + (lrow * 40 + lch) * 2, Kp + (size_t)gk * DM + lch, pr);
                cp16(vsb + sb * TILE_B + (lrow * 40 + lch) * 2, Vg + (size_t)gk * DM + lch, pr);
            }
            CP_COMMIT();
        }
        int sb = kt % 3;
        uint32_t kb_ = ksb + sb * TILE_B;
        uint32_t vb_ = vsb + sb * TILE_B;
        int j0 = kt << 6;

        float sacc[8][4] = {};
#pragma unroll
        for (int ks = 0; ks < 2; ks++) {
#pragma unroll
            for (int i = 0; i < 4; i++) {
                uint32_t br[4];
                ldsm_x4(br, kb_ + ((i * 16 + aro) * 40 + ks * 16 + akh) * 2);
                mma_bf16(sacc[2 * i],     qf[ks], br[0], br[2]);
                mma_bf16(sacc[2 * i + 1], qf[ks], br[1], br[3]);
            }
        }
        if (j0 + 64 > kc) {
#pragma unroll
            for (int jn = 0; jn < 8; jn++)
                if (j0 + 8 * jn >= kc) {
                    sacc[jn][0] = -1e30f; sacc[jn][1] = -1e30f;
                    sacc[jn][2] = -1e30f; sacc[jn][3] = -1e30f;
                }
        }
#pragma unroll
        for (int jn = 0; jn < 8; jn++) {
            float p0 = mufu_ex2(sacc[jn][0]);
            float p1 = mufu_ex2(sacc[jn][1]);
            float p2 = mufu_ex2(sacc[jn][2]);
            float p3 = mufu_ex2(sacc[jn][3]);
            sacc[jn][0] = p0; sacc[jn][1] = p1; sacc[jn][2] = p2; sacc[jn][3] = p3;
            lsum[0] += p0 + p1;
            lsum[1] += p2 + p3;
        }
#pragma unroll
        for (int s = 0; s < 4; s++) {
            uint32_t pf[4];
            pf[0] = pack_bf16(sacc[2 * s][0], sacc[2 * s][1]);
            pf[1] = pack_bf16(sacc[2 * s][2], sacc[2 * s][3]);
            pf[2] = pack_bf16(sacc[2 * s + 1][0], sacc[2 * s + 1][1]);
            pf[3] = pack_bf16(sacc[2 * s + 1][2], sacc[2 * s + 1][3]);
#pragma unroll
            for (int dv = 0; dv < 2; dv++) {
                uint32_t br[4];
                ldsm_x4t(br, vb_ + ((s * 16 + aro) * 40 + dv * 16 + akh) * 2);
                mma_bf16(oacc[2 * dv],     pf, br[0], br[1]);
                mma_bf16(oacc[2 * dv + 1], pf, br[2], br[3]);
            }
        }
    }

    lsum[0] += __shfl_xor_sync(0xffffffffu, lsum[0], 1);
    lsum[0] += __shfl_xor_sync(0xffffffffu, lsum[0], 2);
    lsum[1] += __shfl_xor_sync(0xffffffffu, lsum[1], 1);
    lsum[1] += __shfl_xor_sync(0xffffffffu, lsum[1], 2);
    float inv0 = __fdividef(1.0f, lsum[0]);
    float inv1 = __fdividef(1.0f, lsum[1]);

    int qr0 = q0 + warp * 16 + g;
    int qr1 = qr0 + 8;
    if (qr0 < kc) {
        __nv_bfloat16* op = O + ((size_t)b * kc + qr0) * DM + hh * DH;
#pragma unroll
        for (int dn = 0; dn < 4; dn++)
            *(uint32_t*)(op + 8 * dn + 2 * tg) = pack_bf16(oacc[dn][0] * inv0, oacc[dn][1] * inv0);
    }
    if (qr1 < kc) {
        __nv_bfloat16* op = O + ((size_t)b * kc + qr1) * DM + hh * DH;
#pragma unroll
        for (int dn = 0; dn < 4; dn++)
            *(uint32_t*)(op + 8 * dn + 2 * tg) = pack_bf16(oacc[dn][2] * inv1, oacc[dn][3] * inv1);
    }
}

// ---------------- launch ----------------
extern "C" void kernel_launch(void* const* d_in, const int* in_sizes, int n_in,
                              void* d_out, int out_size) {
    const float* feat = (const float*)d_in[0];
    const float* sal  = (const float*)d_in[1];
    const float* Wq   = (const float*)d_in[2];
    const float* Wk   = (const float*)d_in[3];
    const float* Wv   = (const float*)d_in[4];
    const float* Wo   = (const float*)d_in[5];
    const float* W1   = (const float*)d_in[6];
    const float* W2   = (const float*)d_in[7];
    const float* g1   = (const float*)d_in[8];
    const float* b1   = (const float*)d_in[9];
    const float* g2   = (const float*)d_in[10];
    const float* b2   = (const float*)d_in[11];
    float* out = (float*)d_out;

    float *px, *ph, *pq, *pk, *pv, *pa, *pf;
    __nv_bfloat16* pwb;
    int* pidx;
    cudaGetSymbolAddress((void**)&px, g_x);
    cudaGetSymbolAddress((void**)&ph, g_h);
    cudaGetSymbolAddress((void**)&pq, g_q);
    cudaGetSymbolAddress((void**)&pk, g_k);
    cudaGetSymbolAddress((void**)&pv, g_v);
    cudaGetSymbolAddress((void**)&pa, g_a);
    cudaGetSymbolAddress((void**)&pf, g_f);
    cudaGetSymbolAddress((void**)&pwb, g_wb);
    cudaGetSymbolAddress((void**)&pidx, g_idx);

    __nv_bfloat16* hb = (__nv_bfloat16*)ph;
    __nv_bfloat16* qb = (__nv_bfloat16*)pq;
    __nv_bfloat16* kb = (__nv_bfloat16*)pk;
    __nv_bfloat16* vb = (__nv_bfloat16*)pv;
    __nv_bfloat16* ab = (__nv_bfloat16*)pa;
    __nv_bfloat16* fb = (__nv_bfloat16*)pf;

    // 1/sqrt(32) * log2(e): softmax done in exp2 domain
    const float qscale = 0.17677669529663687f * 1.4426950408889634f;
    const int n4 = NB * NTOK * DM / 4;
    copy_kernel<<<(n4 + 255) / 256, 256>>>((const float4*)feat, (float4*)out, n4);
    rank_kernel<<<dim3((NTOK + 255) / 256, NB), 256>>>(sal, pidx);
    cvtw_kernel<<<WB_TOTAL / 4 / 256, 256>>>((const float4*)Wq, (const float4*)Wk,
                                             (const float4*)Wv, (const float4*)Wo,
                                             (const float4*)W1, (const float4*)W2, (uint2*)pwb);

    static const int KCNT[4] = {3200, 2400, 2000, 1600};
    for (int l = 0; l < 4; l++) {
        int kc = KCNT[l];
        int M = NB * kc;
        int gx128 = (M + 127) / 128;
        int gx64 = (M + 63) / 64;
        const __nv_bfloat16* wq_l = pwb + (size_t)l * 65536;
        const __nv_bfloat16* wk_l = pwb + WK_OFF + (size_t)l * 65536;
        const __nv_bfloat16* wv_l = pwb + WV_OFF + (size_t)l * 65536;
        const __nv_bfloat16* wo_l = pwb + WO_OFF + (size_t)l * 65536;
        const __nv_bfloat16* w1_l = pwb + W1_OFF + (size_t)l * 262144;
        const __nv_bfloat16* w2_l = pwb + W2_OFF + (size_t)l * 262144;

        if (l == 0)
            lnw_kernel<1><<<(M + 15) / 16, 256>>>(out, pidx, g1, b1, px, hb, kc, M);
        else
            lnw_kernel<0><<<(M + 15) / 16, 256>>>(px, nullptr, g1 + l * DM, b1 + l * DM, nullptr, hb, kc, M);
        qkvb_kernel<<<dim3(gx128, 12), 256>>>(hb, wq_l, wk_l, wv_l, qb, kb, vb, M, kc, qscale);
        attn_mma_kernel<<<dim3((kc + 127) / 128, NH, NB), 256>>>(qb, kb, vb, ab, kc);
        bgemm_kernel<64, 1, 0, 1><<<dim3(gx64, 4), 128>>>(ab, wo_l, px, M, DM, DM, kc);
        lnw_kernel<0><<<(M + 15) / 16, 256>>>(px, nullptr, g2 + l * DM, b2 + l * DM, nullptr, hb, kc, M);
        bgemm_kernel<128, 2, 1, 0><<<dim3(gx128, 16), 256>>>(hb, w1_l, fb, M, 4 * DM, DM, kc);
        bgemm_kernel<64, 1, 0, 1><<<dim3(gx64, 4), 128>>>(fb, w2_l, px, M, DM, 4 * DM, kc);
    }
    fscatter_kernel<<<(NB * KMAX + 7) / 8, 256>>>(px, pidx, out);
}